// round 13
// baseline (speedup 1.0000x reference)
#include <cuda_runtime.h>
#include <cuda_bf16.h>

// AbsolutePositionEncoding: out[b, s, :] = E[s / 8, :]
//   x: [64, 2048] fp32 (shape only, unused)
//   E: [512, 256] fp32 (only rows 0..255 are referenced: 2047/8 = 255)
//   out: [64, 2048, 256] fp32 (128 MiB)
//
// R9 ncu: DRAM 45.8%, L2 55.6%, L1 63.6%, issue 8.2% — nothing saturated.
// Diagnosis: (a) per-iteration LDG doubled L1tex wavefront traffic vs stores;
// (b) __stcs encouraged draining an output that ~fits in L2 and is rewritten
// every graph replay. Fix: register-replay + default store policy.
//
// One thread per (b, obj, vec) triple: load E[obj] float4 ONCE, then store it
// to the 8 consecutive seq rows sharing that obj (address stride 64 float4 =
// 1 KiB). Inner loop is store-only: 8 independent front-batched STG.128.
// Warp lanes cover contiguous vec -> each STG.128 is a 512B contiguous
// segment (perfect coalescing, 4 L1 wavefronts per warp store).

static constexpr int SEQ_LEN       = 2048;
static constexpr int ATTRS         = 8;
static constexpr int OBJS_USED     = SEQ_LEN / ATTRS;       // 256
static constexpr int VECS_PER_ROW  = 256 / 4;               // 64 float4 per row
static constexpr int BATCH         = 64;

static constexpr int THREADS = 256;
static constexpr int TOTAL_THREADS = BATCH * OBJS_USED * VECS_PER_ROW; // 1,048,576
static constexpr int BLOCKS  = TOTAL_THREADS / THREADS;                // 4096
static_assert(BLOCKS * THREADS == TOTAL_THREADS, "exact cover");

__global__ __launch_bounds__(THREADS)
void ape_kernel(const float4* __restrict__ E4, float4* __restrict__ out4)
{
    unsigned t   = blockIdx.x * THREADS + threadIdx.x;
    unsigned vec = t & (VECS_PER_ROW - 1);      // 0..63
    unsigned u   = t >> 6;
    unsigned obj = u & (OBJS_USED - 1);         // 0..255
    unsigned b   = u >> 8;                      // 0..63

    // Single gather (L1/L2-resident; each line reused ~512x across threads).
    float4 v = __ldg(&E4[obj * VECS_PER_ROW + vec]);

    // 8 seq rows share this obj: out[(b*2048 + obj*8 + s)*64 + vec]
    float4* dst = out4 + ((b * SEQ_LEN + obj * ATTRS) * VECS_PER_ROW + vec);

    #pragma unroll
    for (int s = 0; s < ATTRS; s++)
        dst[s * VECS_PER_ROW] = v;              // default policy: stay in L2
}

extern "C" void kernel_launch(void* const* d_in, const int* in_sizes, int n_in,
                              void* d_out, int out_size)
{
    // d_in[0] = x (unused), d_in[1] = E_absolute_position [512, 256] fp32
    const float4* E4 = (const float4*)d_in[1];
    float4* out4 = (float4*)d_out;
    ape_kernel<<<BLOCKS, THREADS>>>(E4, out4);
}